// round 17
// baseline (speedup 1.0000x reference)
#include <cuda_runtime.h>
#include <cuda_bf16.h>
#include <cstdint>

#define NB   8
#define NKB  16
#define SEQL 512
#define HIDD 768
#define BM   128
#define BN   128
#define BK   32
#define NCH  (HIDD / BK)      // 24
#define NST  (SEQL / BM)      // 4
#define NTT  (SEQL / BN)      // 4
#define NTILES (NB * NKB * NST * NTT)   // 2048
#define NPCTA 304             // persistent CTAs (2 per SM)
#define ROWB 80               // padded smem row stride (conflict-free LDSM)
#define ABYTES (BM * ROWB)
#define BBYTES (BN * ROWB)
#define BUF_BYTES (2 * ABYTES + 2 * BBYTES)   // 40960

#define SM_DTAB 0
#define SM_KMF  2048
#define SM_TIDX 2560
#define SM_SIDX 3072
#define SM_RS1  3584
#define SM_RS2  4096
#define SM_BUF  4608
#define SMEM_TOTAL (SM_BUF + 2 * BUF_BYTES)   // 86528

// ---- scratch (compacted layouts) ----
__device__ __nv_bfloat16 g_qh[NB * SEQL * HIDD];
__device__ __nv_bfloat16 g_ql[NB * SEQL * HIDD];
__device__ __nv_bfloat16 g_kh[NKB * SEQL * HIDD];
__device__ __nv_bfloat16 g_kl[NKB * SEQL * HIDD];
__device__ float g_pS1[NB * NKB * NST * NTT * BM];
__device__ float g_pS2[NB * NKB * NST * NTT * BM];
__device__ int g_spos[NB * SEQL], g_tpos[NKB * SEQL];
__device__ int g_sidx[NB * SEQL], g_tidx[NKB * SEQL];
__device__ int g_scnt[NB], g_kcnt[NKB];
__device__ int g_tile_ctr;

// ---------------------------------------------------------------------------
__device__ __forceinline__ uint32_t smem_to_u32(const void* p) {
    uint32_t a;
    asm("{ .reg .u64 t; cvta.to.shared.u64 t, %1; cvt.u32.u64 %0, t; }" : "=r"(a) : "l"(p));
    return a;
}
#define CP16(sa, ga) \
    asm volatile("cp.async.cg.shared.global [%0], [%1], 16;" :: "r"(sa), "l"(ga))
#define CP_COMMIT() asm volatile("cp.async.commit_group;" ::: "memory")
#define CP_WAIT(n)  asm volatile("cp.async.wait_group %0;" :: "n"(n) : "memory")
#define LDSM4(r, addr) \
    asm volatile("ldmatrix.sync.aligned.m8n8.x4.shared.b16 {%0,%1,%2,%3}, [%4];" \
        : "=r"((r)[0]), "=r"((r)[1]), "=r"((r)[2]), "=r"((r)[3]) : "r"(addr))

__device__ __forceinline__ void mma_bf16(float* c, const uint32_t* a, const uint32_t* b) {
    asm volatile(
        "mma.sync.aligned.m16n8k16.row.col.f32.bf16.bf16.f32 "
        "{%0,%1,%2,%3}, {%4,%5,%6,%7}, {%8,%9}, {%0,%1,%2,%3};"
        : "+f"(c[0]), "+f"(c[1]), "+f"(c[2]), "+f"(c[3])
        : "r"(a[0]), "r"(a[1]), "r"(a[2]), "r"(a[3]), "r"(b[0]), "r"(b[1]));
}

// ---------------------------------------------------------------------------
// Mask prefix-scan: compact<->orig maps + counts. Also resets tile counter.
// ---------------------------------------------------------------------------
__global__ __launch_bounds__(512) void scan_kernel(const int* __restrict__ qm,
                                                   const int* __restrict__ km) {
    const int b = blockIdx.x;
    const bool isq = (b < NB);
    const int* m = isq ? (qm + b * SEQL) : (km + (b - NB) * SEQL);
    int* pos = isq ? (g_spos + b * SEQL) : (g_tpos + (b - NB) * SEQL);
    int* idx = isq ? (g_sidx + b * SEQL) : (g_tidx + (b - NB) * SEQL);
    __shared__ int sc[SEQL];
    const int tid = threadIdx.x;
    if (b == 0 && tid == 0) g_tile_ctr = 0;       // reset work queue each launch
    const int v = (m[tid] != 0);
    sc[tid] = v;
    __syncthreads();
    for (int o = 1; o < SEQL; o <<= 1) {
        int t = (tid >= o) ? sc[tid - o] : 0;
        __syncthreads();
        sc[tid] += t;
        __syncthreads();
    }
    const int incl = sc[tid];
    const int total = sc[SEQL - 1];
    if (v) { pos[tid] = incl - 1; idx[incl - 1] = tid; }
    else pos[tid] = -1;
    if (tid >= total) idx[tid] = 0;   // disjoint from scatter range
    if (tid == 0) { if (isq) g_scnt[b] = total; else g_kcnt[b - NB] = total; }
}

// ---------------------------------------------------------------------------
// L2 normalize + bf16 hi/lo split, scattered to compacted position
// ---------------------------------------------------------------------------
__device__ __forceinline__ void norm_split(const float* __restrict__ src,
                                           __nv_bfloat16* __restrict__ hid,
                                           __nv_bfloat16* __restrict__ lod) {
    float v[3];
    float s = 0.f;
#pragma unroll
    for (int c = 0; c < 3; c++) {
        v[c] = src[threadIdx.x + c * 256];
        s += v[c] * v[c];
    }
#pragma unroll
    for (int o = 16; o; o >>= 1) s += __shfl_xor_sync(0xffffffffu, s, o);
    __shared__ float ws[8];
    __shared__ float s_inv;
    if ((threadIdx.x & 31) == 0) ws[threadIdx.x >> 5] = s;
    __syncthreads();
    if (threadIdx.x == 0) {
        float t = 0.f;
#pragma unroll
        for (int w = 0; w < 8; w++) t += ws[w];
        s_inv = 1.f / fmaxf(sqrtf(t), 1e-12f);
    }
    __syncthreads();
    float iv = s_inv;
#pragma unroll
    for (int c = 0; c < 3; c++) {
        float x = v[c] * iv;
        __nv_bfloat16 h = __float2bfloat16(x);
        float lo = x - __bfloat162float(h);
        hid[threadIdx.x + c * 256] = h;
        lod[threadIdx.x + c * 256] = __float2bfloat16(lo);
    }
}
__global__ __launch_bounds__(256) void norm_q_kernel(const float* __restrict__ in,
                                                     const int* __restrict__ qm) {
    const int row = blockIdx.x;             // i*512+s
    if (qm[row] == 0) return;               // block-uniform
    const int i = row >> 9;
    const size_t dst = (size_t)i * SEQL + g_spos[row];
    norm_split(in + (size_t)row * HIDD, g_qh + dst * HIDD, g_ql + dst * HIDD);
}
__global__ __launch_bounds__(256) void norm_k_kernel(const float* __restrict__ in,
                                                     const int* __restrict__ km) {
    const int row = blockIdx.x;
    if (km[row] == 0) return;
    const int j = row >> 9;
    const size_t dst = (size_t)j * SEQL + g_tpos[row];
    norm_split(in + (size_t)row * HIDD, g_kh + dst * HIDD, g_kl + dst * HIDD);
}

// ---------------------------------------------------------------------------
// Zero-fill padding rows up to the next 128-tile boundary (parallel over y)
// ---------------------------------------------------------------------------
__global__ __launch_bounds__(256) void pad_zero_kernel() {
    const int b = blockIdx.x;
    const bool isq = (b < NB);
    const int cnt = isq ? g_scnt[b] : g_kcnt[b - NB];
    int pad = (cnt + 127) & ~127;
    if (pad > SEQL) pad = SEQL;
    __nv_bfloat16* h = isq ? (g_qh + (size_t)b * SEQL * HIDD)
                           : (g_kh + (size_t)(b - NB) * SEQL * HIDD);
    __nv_bfloat16* l = isq ? (g_ql + (size_t)b * SEQL * HIDD)
                           : (g_kl + (size_t)(b - NB) * SEQL * HIDD);
    const int n = (pad - cnt) * HIDD;
    const __nv_bfloat16 z = __float2bfloat16(0.f);
    const int start = blockIdx.y * 256 + threadIdx.x;
    const int stride = gridDim.y * 256;
    for (int e = start; e < n; e += stride) {
        h[(size_t)cnt * HIDD + e] = z;
        l[(size_t)cnt * HIDD + e] = z;
    }
}

// ---------------------------------------------------------------------------
// Main: PERSISTENT bf16x3 mma.sync GEMM + fused softmax-score.
// Tiles pulled from a global atomic work queue (deterministic outputs:
// tile->slot mapping is fixed; stealing only changes who computes it).
// ---------------------------------------------------------------------------
__global__ __launch_bounds__(256, 2) void li_mma_kernel(
    const float* __restrict__ alpha_p) {

    extern __shared__ char smem[];
    __shared__ int s_slot;
    const uint32_t sb = smem_to_u32(smem);
    const int tid = threadIdx.x;
    const int lane = tid & 31;
    const int w = tid >> 5;
    const int warp_m = w & 3;
    const int warp_n = w >> 2;

    float* dtab = (float*)(smem + SM_DTAB);
    float* kmf  = (float*)(smem + SM_KMF);
    int*   tdx  = (int*)(smem + SM_TIDX);
    int*   sdx  = (int*)(smem + SM_SIDX);
    float* rs1s = (float*)(smem + SM_RS1);
    float* rs2s = (float*)(smem + SM_RS2);

    // decay table: once per CTA, reused for all tiles
    {
        float ar = *alpha_p;
        float alpha = (ar > 0.f) ? ar : 0.01f * ar;
        for (int d = tid; d < SEQL; d += 256) dtab[d] = __expf(-alpha * (float)d);
    }

    while (true) {
        if (tid == 0) s_slot = atomicAdd(&g_tile_ctr, 1);
        __syncthreads();
        const int slot = s_slot;
        __syncthreads();
        if (slot >= NTILES) break;

        const int ij = slot >> 4;
        const int stile = (slot >> 2) & 3;
        const int ttile = slot & 3;
        const int i = ij >> 4, j = ij & 15;
        const int s0 = stile * BM, t0 = ttile * BN;

        const int scnt = g_scnt[i], kcnt = g_kcnt[j];
        const int qtiles = (scnt + BM - 1) >> 7;
        const int ktiles = (kcnt + BN - 1) >> 7;
        if (stile >= qtiles || ttile >= ktiles) continue;   // finalize never reads

        const size_t pidx0 = (((size_t)ij * NST + stile) * NTT + ttile) * BM;

        // per-tile tables
        if (tid < BN) {
            kmf[tid] = (t0 + tid < kcnt) ? 1.f : 0.f;
            tdx[tid] = g_tidx[j * SEQL + t0 + tid];
        }
        if (tid >= BN && tid < BN + BM) {
            const int r = tid - BN;
            sdx[r] = g_sidx[i * SEQL + s0 + r];
            rs1s[r] = 0.f; rs2s[r] = 0.f;
        }
        __syncthreads();

        const __nv_bfloat16* Ah = g_qh + ((size_t)i * SEQL + s0) * HIDD;
        const __nv_bfloat16* Al = g_ql + ((size_t)i * SEQL + s0) * HIDD;
        const __nv_bfloat16* Bh = g_kh + ((size_t)j * SEQL + t0) * HIDD;
        const __nv_bfloat16* Bl = g_kl + ((size_t)j * SEQL + t0) * HIDD;

        float acc[2][8][4];
#pragma unroll
        for (int mi = 0; mi < 2; mi++)
#pragma unroll
            for (int ni = 0; ni < 8; ni++)
#pragma unroll
                for (int e = 0; e < 4; e++) acc[mi][ni][e] = 0.f;

        auto load_chunk = [&](int ch, int b) {
            const uint32_t base = sb + SM_BUF + b * BUF_BYTES;
            const int k0 = ch * BK;
#pragma unroll
            for (int half = 0; half < 2; half++) {
                const int idx = tid + half * 256;
                const int row = idx >> 2, q = idx & 3;
                const size_t go = (size_t)row * HIDD + k0 + q * 8;
                const uint32_t so = base + row * ROWB + q * 16;
                CP16(so, Ah + go);
                CP16(so + ABYTES, Al + go);
                const uint32_t so2 = base + 2 * ABYTES + row * ROWB + q * 16;
                CP16(so2, Bh + go);
                CP16(so2 + BBYTES, Bl + go);
            }
        };

        auto mma_chunk = [&](int b) {
            const uint32_t abase = sb + SM_BUF + b * BUF_BYTES;
            const uint32_t bbase = abase + 2 * ABYTES;
#pragma unroll
            for (int ks = 0; ks < 2; ks++) {
                const int kb = ks * 32;
                uint32_t ah[2][4], al[2][4];
#pragma unroll
                for (int mi = 0; mi < 2; mi++) {
                    const uint32_t r = warp_m * 32 + mi * 16 + (lane & 15);
                    const uint32_t ad = abase + r * ROWB + kb + (lane >> 4) * 16;
                    LDSM4(ah[mi], ad);
                    LDSM4(al[mi], ad + ABYTES);
                }
#pragma unroll
                for (int nh = 0; nh < 2; nh++) {
                    uint32_t bhr[2][4], blr[2][4];
#pragma unroll
                    for (int bi = 0; bi < 2; bi++) {
                        const int n0 = warp_n * 64 + nh * 32 + bi * 16;
                        const uint32_t rr = n0 + ((lane >> 4) * 8) + (lane & 7);
                        const uint32_t bd = bbase + rr * ROWB + kb + (((lane >> 3) & 1) * 16);
                        LDSM4(bhr[bi], bd);
                        LDSM4(blr[bi], bd + BBYTES);
                    }
                    // pass-outer issue order: same-accumulator MMAs 8 apart
                    // (per-acc addition order hh->hl->lh => bit-identical)
#pragma unroll
                    for (int mi = 0; mi < 2; mi++)
#pragma unroll
                        for (int f = 0; f < 4; f++)
                            mma_bf16(acc[mi][nh * 4 + f], ah[mi],
                                     &bhr[f >> 1][(f & 1) * 2]);          // hi*hi
#pragma unroll
                    for (int mi = 0; mi < 2; mi++)
#pragma unroll
                        for (int f = 0; f < 4; f++)
                            mma_bf16(acc[mi][nh * 4 + f], ah[mi],
                                     &blr[f >> 1][(f & 1) * 2]);          // hi*lo
#pragma unroll
                    for (int mi = 0; mi < 2; mi++)
#pragma unroll
                        for (int f = 0; f < 4; f++)
                            mma_bf16(acc[mi][nh * 4 + f], al[mi],
                                     &bhr[f >> 1][(f & 1) * 2]);          // lo*hi
                }
            }
        };

        load_chunk(0, 0);
        CP_COMMIT();
        for (int ch = 0; ch < NCH; ch++) {
            if (ch + 1 < NCH) {
                load_chunk(ch + 1, (ch + 1) & 1);
                CP_COMMIT();
                CP_WAIT(1);
            } else {
                CP_WAIT(0);
            }
            __syncthreads();
            mma_chunk(ch & 1);
            __syncthreads();
        }

        // ---- fused epilogue with original-index distance decay ----
        float prs1[2][2], prs2[2][2];
#pragma unroll
        for (int mi = 0; mi < 2; mi++)
#pragma unroll
            for (int h = 0; h < 2; h++) { prs1[mi][h] = 0.f; prs2[mi][h] = 0.f; }

#pragma unroll
        for (int mi = 0; mi < 2; mi++) {
            const int rloc = warp_m * 32 + mi * 16 + (lane >> 2);
            const int sor[2] = { sdx[rloc], sdx[rloc + 8] };
#pragma unroll
            for (int ni = 0; ni < 8; ni++) {
                const int tloc = warp_n * 64 + ni * 8 + (lane & 3) * 2;
#pragma unroll
                for (int e = 0; e < 4; e++) {
                    const int sorr = sor[e >> 1];
                    const int torr = tdx[tloc + (e & 1)];
                    const float cv = acc[mi][ni][e];
                    int d = sorr - torr; if (d < 0) d = -d;
                    const float ee = kmf[tloc + (e & 1)] * __expf(cv * dtab[d]);
                    prs1[mi][e >> 1] += ee;
                    prs2[mi][e >> 1] += ee * cv;
                }
            }
        }

#pragma unroll
        for (int mi = 0; mi < 2; mi++)
#pragma unroll
            for (int h = 0; h < 2; h++) {
                float v1 = prs1[mi][h], v2 = prs2[mi][h];
                v1 += __shfl_xor_sync(0xffffffffu, v1, 1);
                v1 += __shfl_xor_sync(0xffffffffu, v1, 2);
                v2 += __shfl_xor_sync(0xffffffffu, v2, 1);
                v2 += __shfl_xor_sync(0xffffffffu, v2, 2);
                if ((lane & 3) == 0) {
                    const int lr = warp_m * 32 + mi * 16 + (lane >> 2) + h * 8;
                    atomicAdd(&rs1s[lr], v1);   // exactly 2 addends/row
                    atomicAdd(&rs2s[lr], v2);   // -> deterministic
                }
            }
        __syncthreads();

        if (tid < BM) {
            g_pS1[pidx0 + tid] = rs1s[tid];
            g_pS2[pidx0 + tid] = rs2s[tid];
        }
        __syncthreads();
    }
}

// ---------------------------------------------------------------------------
// Finalize: count-aware sum over ACTIVE tiles only (pads self-cancel)
// ---------------------------------------------------------------------------
__global__ __launch_bounds__(256) void finalize_kernel(float* __restrict__ out) {
    const int z = blockIdx.x;           // ij = i*16+j
    const int i = z >> 4, j = z & 15;
    const int qtiles = (g_scnt[i] + BM - 1) >> 7;
    const int ktiles = (g_kcnt[j] + BN - 1) >> 7;
    __shared__ float red[256];
    float acc = 0.f;
    for (int s = threadIdx.x; s < qtiles * BM; s += 256) {
        const int stile = s >> 7, r = s & 127;
        const size_t base = (((size_t)z * NST + stile) * NTT) * BM + r;
        float S1 = 0.f, S2 = 0.f;
        for (int tt = 0; tt < ktiles; tt++) {   // fixed order: deterministic
            S1 += g_pS1[base + (size_t)tt * BM];
            S2 += g_pS2[base + (size_t)tt * BM];
        }
        acc += (S1 > 0.f) ? (S2 / S1) : 0.f;
    }
    red[threadIdx.x] = acc;
    __syncthreads();
    for (int o = 128; o; o >>= 1) {
        if (threadIdx.x < (unsigned)o) red[threadIdx.x] += red[threadIdx.x + o];
        __syncthreads();
    }
    if (threadIdx.x == 0) out[z] = red[0];
}

// ---------------------------------------------------------------------------
extern "C" void kernel_launch(void* const* d_in, const int* in_sizes, int n_in,
                              void* d_out, int out_size) {
    const float* q     = (const float*)d_in[0];
    const float* k     = (const float*)d_in[1];
    const float* alpha = (const float*)d_in[2];
    const int*   qm    = (const int*)d_in[3];
    const int*   kmm   = (const int*)d_in[4];
    float* out = (float*)d_out;

    cudaFuncSetAttribute(li_mma_kernel, cudaFuncAttributeMaxDynamicSharedMemorySize,
                         SMEM_TOTAL);

    scan_kernel<<<NB + NKB, 512>>>(qm, kmm);
    norm_q_kernel<<<NB * SEQL, 256>>>(q, qm);
    norm_k_kernel<<<NKB * SEQL, 256>>>(k, kmm);
    {
        dim3 pg(NB + NKB, 16);
        pad_zero_kernel<<<pg, 256>>>();
    }

    li_mma_kernel<<<NPCTA, 256, SMEM_TOTAL>>>(alpha);

    finalize_kernel<<<NB * NKB, 256>>>(out);
}